// round 1
// baseline (speedup 1.0000x reference)
#include <cuda_runtime.h>
#include <math.h>

// Problem constants
#define NT 365
#define NG 512
#define NX 256
#define HH 1024
#define G4 4096

// Tiling
#define BK 16
#define SA_STRIDE 68
#define SB_STRIDE 68

// Scratch (allocation-free: __device__ globals)
__device__ float g_c[NG * HH];                       // cell state
__device__ float g_zero[NG * HH];                    // h_{-1} = 0
__device__ float g_hs[(size_t)NT * NG * HH];         // all hidden states

typedef unsigned long long ull;

__device__ __forceinline__ ull pk2(float x, float y) {
    ull r;
    asm("mov.b64 %0, {%1, %2};" : "=l"(r) : "f"(x), "f"(y));
    return r;
}
__device__ __forceinline__ float2 upk2(ull v) {
    float2 r;
    asm("mov.b64 {%0, %1}, %2;" : "=f"(r.x), "=f"(r.y) : "l"(v));
    return r;
}
__device__ __forceinline__ void fma2(ull& d, ull a, ull b) {
    asm("fma.rn.f32x2 %0, %1, %2, %3;" : "=l"(d) : "l"(a), "l"(b), "l"(d));
}
__device__ __forceinline__ float sigmoidf_(float x) {
    return 1.0f / (1.0f + expf(-x));
}

// Zero the persistent state at the start of every launch (deterministic).
__global__ void zero_state_kernel() {
    int i = blockIdx.x * blockDim.x + threadIdx.x;
    if (i < NG * HH) {
        g_c[i] = 0.0f;
        g_zero[i] = 0.0f;
    }
}

// One LSTM step. Grid: 128 blocks = 8 batch-tiles x 16 hidden-tiles.
// Block computes gates for 64 batch rows x 64 hidden cols x 4 gates,
// fusing input projection (K=256, masked x) and recurrent GEMM (K=1024),
// then applies activations and updates c / writes h.
__global__ __launch_bounds__(256, 1) void lstm_step_kernel(
    const float* __restrict__ x,
    const float* __restrict__ maskX,
    const float* __restrict__ W_ih,
    const float* __restrict__ W_hh,
    const float* __restrict__ b_ih,
    const float* __restrict__ b_hh,
    int t)
{
    __shared__ __align__(16) float sA[BK][SA_STRIDE];       // [k][batch-local]
    __shared__ __align__(16) float sB[4][BK][SB_STRIDE];    // [gate][k][hid-local]

    const int tid = threadIdx.x;
    const int tx = tid & 31;    // 0..31 : hidden col pair index
    const int ty = tid >> 5;    // 0..7  : batch row group
    const int bblk = blockIdx.x & 7;
    const int nblk = blockIdx.x >> 3;
    const int b0 = bblk * 64;
    const int n0 = nblk * 64;

    const float* hprev = (t == 0) ? g_zero : (g_hs + (size_t)(t - 1) * NG * HH);

    ull acc[4][8];
#pragma unroll
    for (int g = 0; g < 4; ++g)
#pragma unroll
        for (int r = 0; r < 8; ++r)
            acc[g][r] = pk2(0.0f, 0.0f);

    // loader coordinates
    const int bl = tid >> 2;             // 0..63 (row within tile)
    const int kk = (tid & 3) << 2;       // 0,4,8,12 (k offset, float4)

    for (int phase = 0; phase < 2; ++phase) {
        const float* Ag = phase ? (hprev + (size_t)b0 * HH)
                                : (x + ((size_t)t * NG + b0) * NX);
        const float* Bg = phase ? W_hh : W_ih;
        const float* Mg = maskX + (size_t)b0 * NX;
        const int Kd = phase ? HH : NX;

        // global B row indices for the 4 chunks this thread loads
        int brow[4];
#pragma unroll
        for (int p = 0; p < 4; ++p) {
            int rr = (tid >> 2) + (p << 6);            // 0..255
            brow[p] = (rr >> 6) * HH + n0 + (rr & 63); // gate*H + n0 + j
        }

        // prologue prefetch
        float4 ra = *(const float4*)(Ag + (size_t)bl * Kd + kk);
        float4 rm;
        if (!phase) rm = *(const float4*)(Mg + (size_t)bl * NX + kk);
        float4 rb[4];
#pragma unroll
        for (int p = 0; p < 4; ++p)
            rb[p] = *(const float4*)(Bg + (size_t)brow[p] * Kd + kk);

        for (int k0 = 0; k0 < Kd; k0 += BK) {
            __syncthreads();   // previous compute done before overwrite

            float4 av = ra;
            if (!phase) { av.x *= rm.x; av.y *= rm.y; av.z *= rm.z; av.w *= rm.w; }
            sA[kk + 0][bl] = av.x;
            sA[kk + 1][bl] = av.y;
            sA[kk + 2][bl] = av.z;
            sA[kk + 3][bl] = av.w;
#pragma unroll
            for (int p = 0; p < 4; ++p) {
                int rr = (tid >> 2) + (p << 6);
                int g = rr >> 6, j = rr & 63;
                sB[g][kk + 0][j] = rb[p].x;
                sB[g][kk + 1][j] = rb[p].y;
                sB[g][kk + 2][j] = rb[p].z;
                sB[g][kk + 3][j] = rb[p].w;
            }
            __syncthreads();

            // prefetch next slice (hidden behind compute)
            const int kn = k0 + BK;
            if (kn < Kd) {
                ra = *(const float4*)(Ag + (size_t)bl * Kd + kn + kk);
                if (!phase) rm = *(const float4*)(Mg + (size_t)bl * NX + kn + kk);
#pragma unroll
                for (int p = 0; p < 4; ++p)
                    rb[p] = *(const float4*)(Bg + (size_t)brow[p] * Kd + kn + kk);
            }

            // compute: 8 rows x 2 cols x 4 gates per thread, packed f32x2
#pragma unroll
            for (int k = 0; k < BK; ++k) {
                const float4 a0 = *(const float4*)&sA[k][ty * 8];
                const float4 a1 = *(const float4*)&sA[k][ty * 8 + 4];
                ull aa[8];
                aa[0] = pk2(a0.x, a0.x); aa[1] = pk2(a0.y, a0.y);
                aa[2] = pk2(a0.z, a0.z); aa[3] = pk2(a0.w, a0.w);
                aa[4] = pk2(a1.x, a1.x); aa[5] = pk2(a1.y, a1.y);
                aa[6] = pk2(a1.z, a1.z); aa[7] = pk2(a1.w, a1.w);
                ull bg[4];
#pragma unroll
                for (int g = 0; g < 4; ++g)
                    bg[g] = *(const ull*)&sB[g][k][tx * 2];
#pragma unroll
                for (int g = 0; g < 4; ++g)
#pragma unroll
                    for (int r = 0; r < 8; ++r)
                        fma2(acc[g][r], aa[r], bg[g]);
            }
        }
    }

    // Epilogue: bias + activations + state update
    const int brow0 = b0 + ty * 8;
    const int col0 = n0 + tx * 2;
    float2 biasv[4];
#pragma unroll
    for (int g = 0; g < 4; ++g) {
        float2 u = *(const float2*)&b_ih[g * HH + col0];
        float2 v = *(const float2*)&b_hh[g * HH + col0];
        biasv[g].x = u.x + v.x;
        biasv[g].y = u.y + v.y;
    }
    float* hout = g_hs + (size_t)t * NG * HH;

#pragma unroll
    for (int r = 0; r < 8; ++r) {
        const int b = brow0 + r;
        float2 ip = upk2(acc[0][r]);
        float2 fp = upk2(acc[1][r]);
        float2 gp = upk2(acc[2][r]);
        float2 op = upk2(acc[3][r]);
        float2 c = *(float2*)&g_c[(size_t)b * HH + col0];

        float i0 = sigmoidf_(ip.x + biasv[0].x);
        float i1 = sigmoidf_(ip.y + biasv[0].y);
        float f0 = sigmoidf_(fp.x + biasv[1].x);
        float f1 = sigmoidf_(fp.y + biasv[1].y);
        float gg0 = tanhf(gp.x + biasv[2].x);
        float gg1 = tanhf(gp.y + biasv[2].y);
        float o0 = sigmoidf_(op.x + biasv[3].x);
        float o1 = sigmoidf_(op.y + biasv[3].y);

        float c0 = f0 * c.x + i0 * gg0;
        float c1 = f1 * c.y + i1 * gg1;
        float h0 = o0 * tanhf(c0);
        float h1 = o1 * tanhf(c1);

        *(float2*)&g_c[(size_t)b * HH + col0] = make_float2(c0, c1);
        *(float2*)&hout[(size_t)b * HH + col0] = make_float2(h0, h1);
    }
}

// out[t,b] = dot(hs[t,b,:], W_lin) + b_lin ; one warp per row.
__global__ void out_kernel(const float* __restrict__ W_lin,
                           const float* __restrict__ b_lin,
                           float* __restrict__ out)
{
    const int warp = (blockIdx.x * blockDim.x + threadIdx.x) >> 5;
    const int lane = threadIdx.x & 31;
    if (warp >= NT * NG) return;
    const float* hrow = g_hs + (size_t)warp * HH;
    float s = 0.0f;
#pragma unroll
    for (int j = lane; j < HH; j += 32)
        s += hrow[j] * W_lin[j];
#pragma unroll
    for (int o = 16; o; o >>= 1)
        s += __shfl_xor_sync(0xFFFFFFFFu, s, o);
    if (lane == 0) out[warp] = s + b_lin[0];
}

extern "C" void kernel_launch(void* const* d_in, const int* in_sizes, int n_in,
                              void* d_out, int out_size)
{
    const float* x     = (const float*)d_in[0];  // [NT,NG,NX]
    const float* maskX = (const float*)d_in[1];  // [NG,NX]
    const float* W_ih  = (const float*)d_in[2];  // [4H,NX]
    const float* W_hh  = (const float*)d_in[3];  // [4H,H]
    const float* b_ih  = (const float*)d_in[4];  // [4H]
    const float* b_hh  = (const float*)d_in[5];  // [4H]
    const float* W_lin = (const float*)d_in[6];  // [1,H]
    const float* b_lin = (const float*)d_in[7];  // [1]
    float* out = (float*)d_out;                  // [NT,NG,1]

    // 1) zero persistent state (deterministic per launch)
    zero_state_kernel<<<(NG * HH + 255) / 256, 256>>>();

    // 2) 365 sequential LSTM steps
    for (int t = 0; t < NT; ++t) {
        lstm_step_kernel<<<128, 256>>>(x, maskX, W_ih, W_hh, b_ih, b_hh, t);
    }

    // 3) output projection
    const int rows = NT * NG;
    const int warps_per_block = 256 / 32;
    out_kernel<<<(rows + warps_per_block - 1) / warps_per_block, 256>>>(W_lin, b_lin, out);
}

// round 5
// speedup vs baseline: 2.0845x; 2.0845x over previous
#include <cuda_runtime.h>
#include <cuda_bf16.h>
#include <stdint.h>
#include <math.h>

#define NT 365
#define NG 512
#define NX 256
#define HH 1024
#define KTOT 1280
#define G4 4096
#define NGHH (NG * HH)
#define NCHUNK 20                    // 16 chunks of h (K=1024) + 4 of xm (K=256), 64 each
#define STAGE_BYTES 65536            // Ahi/Alo/Bhi/Blo tiles, 16KB each (128 rows x 128B)
#define DSMEM_BYTES (2 * STAGE_BYTES)

// ---------------- scratch (__device__ globals; no allocation) ----------------
__device__ float g_c[NGHH];
__device__ float g_hs[(size_t)NT * NGHH];
__device__ __nv_bfloat16 g_h_hi[2][NGHH];             // ping-pong across steps
__device__ __nv_bfloat16 g_h_lo[2][NGHH];
__device__ __nv_bfloat16 g_Wp_hi[(size_t)G4 * KTOT];  // rows permuted: r' = col*4 + gate
__device__ __nv_bfloat16 g_Wp_lo[(size_t)G4 * KTOT];
__device__ __nv_bfloat16 g_xm_hi[(size_t)NT * NG * NX];
__device__ __nv_bfloat16 g_xm_lo[(size_t)NT * NG * NX];
__device__ float4 g_biasp[HH];                        // per col: (bi, bf, bg, bo)

// ---------------- PTX helpers ----------------
static __device__ __forceinline__ uint32_t smem_u32(const void* p) {
    uint32_t a;
    asm("{ .reg .u64 t; cvta.to.shared.u64 t, %1; cvt.u32.u64 %0, t; }" : "=r"(a) : "l"(p));
    return a;
}
#define SWZ(o) ((o) ^ (((o) >> 3) & 0x70))

static __device__ __forceinline__ void cp16(uint32_t dst, const void* src) {
    asm volatile("cp.async.cg.shared.global [%0], [%1], 16;" :: "r"(dst), "l"(src));
}
static __device__ __forceinline__ void cp_commit() {
    asm volatile("cp.async.commit_group;" ::: "memory");
}
template <int N>
static __device__ __forceinline__ void cp_wait() {
    asm volatile("cp.async.wait_group %0;" :: "n"(N) : "memory");
}
static __device__ __forceinline__ void ldm4(uint32_t* r, uint32_t addr) {
    asm volatile("ldmatrix.sync.aligned.m8n8.x4.shared.b16 {%0,%1,%2,%3}, [%4];"
                 : "=r"(r[0]), "=r"(r[1]), "=r"(r[2]), "=r"(r[3]) : "r"(addr));
}
static __device__ __forceinline__ void mma_bf16(float* d, const uint32_t* a,
                                                uint32_t b0, uint32_t b1) {
    asm volatile(
        "mma.sync.aligned.m16n8k16.row.col.f32.bf16.bf16.f32 "
        "{%0,%1,%2,%3}, {%4,%5,%6,%7}, {%8,%9}, {%0,%1,%2,%3};"
        : "+f"(d[0]), "+f"(d[1]), "+f"(d[2]), "+f"(d[3])
        : "r"(a[0]), "r"(a[1]), "r"(a[2]), "r"(a[3]), "r"(b0), "r"(b1));
}
__device__ __forceinline__ float sigmoidf_(float x) { return 1.0f / (1.0f + expf(-x)); }

// ---------------- prep kernels ----------------
__global__ void zero_kernel() {
    int i = blockIdx.x * 256 + threadIdx.x;
    if (i < NGHH) {
        g_c[i] = 0.0f;
        g_h_hi[0][i] = __float2bfloat16(0.0f);
        g_h_lo[0][i] = __float2bfloat16(0.0f);
    }
}

__global__ void prep_bias_kernel(const float* __restrict__ b_ih, const float* __restrict__ b_hh) {
    int col = blockIdx.x * 256 + threadIdx.x;
    if (col >= HH) return;
    float4 v;
    v.x = b_ih[col] + b_hh[col];
    v.y = b_ih[HH + col] + b_hh[HH + col];
    v.z = b_ih[2 * HH + col] + b_hh[2 * HH + col];
    v.w = b_ih[3 * HH + col] + b_hh[3 * HH + col];
    g_biasp[col] = v;
}

// W' row r' = col*4 + gate; k cols 0..1023 from W_hh, 1024..1279 from W_ih (fused K)
__global__ void prep_W_kernel(const float* __restrict__ W_ih, const float* __restrict__ W_hh) {
    int k = blockIdx.x * 256 + threadIdx.x;
    int r = blockIdx.y;                       // old row: gate*1024 + col
    if (k >= KTOT) return;
    float v = (k < HH) ? W_hh[(size_t)r * HH + k]
                       : W_ih[(size_t)r * NX + (k - HH)];
    __nv_bfloat16 hi = __float2bfloat16(v);
    __nv_bfloat16 lo = __float2bfloat16(v - __bfloat162float(hi));
    int gate = r >> 10, col = r & 1023;
    size_t rp = (size_t)(col * 4 + gate) * KTOT + k;
    g_Wp_hi[rp] = hi;
    g_Wp_lo[rp] = lo;
}

__global__ void prep_xm_kernel(const float* __restrict__ x, const float* __restrict__ maskX) {
    int idx = blockIdx.x * 256 + threadIdx.x;   // 0..NG*NX-1
    int t = blockIdx.y;
    size_t gi = (size_t)t * (NG * NX) + idx;
    float v = x[gi] * maskX[idx];
    __nv_bfloat16 hi = __float2bfloat16(v);
    __nv_bfloat16 lo = __float2bfloat16(v - __bfloat162float(hi));
    g_xm_hi[gi] = hi;
    g_xm_lo[gi] = lo;
}

// ---------------- fused step: GEMM (split-bf16 3-term) + cell epilogue ----------------
// grid 128 = 4 m-groups(128 batch) x 32 col-groups(32 hidden cols x 4 gates = 128 N)
__global__ __launch_bounds__(256, 1) void lstm_step_kernel(int t) {
    extern __shared__ char dsm[];
    const uint32_t sbase = smem_u32(dsm);
    const int tid = threadIdx.x;
    const int w = tid >> 5;
    const int lane = tid & 31;
    const int m0 = (blockIdx.x & 3) * 128;
    const int cgrp = blockIdx.x >> 2;
    const int n0g = cgrp * 128;                 // W' row base (contiguous after permute)
    const int rbuf = t & 1;
    const int wbuf = (t + 1) & 1;

    const int prow = tid >> 3;                  // cp.async: 0..31 (+32*s)
    const int pseg = tid & 7;                   // 16B segment in 128B row

    float acc[2][8][4];
#pragma unroll
    for (int im = 0; im < 2; ++im)
#pragma unroll
        for (int jn = 0; jn < 8; ++jn)
#pragma unroll
            for (int r = 0; r < 4; ++r) acc[im][jn][r] = 0.0f;

    auto prefetch = [&](int i, int stage) {
        const uint32_t stb = sbase + stage * STAGE_BYTES;
        const __nv_bfloat16 *aHi, *aLo;
        int astr, ak;
        if (i < 16) {
            aHi = g_h_hi[rbuf]; aLo = g_h_lo[rbuf]; astr = HH; ak = i * 64;
        } else {
            size_t off = (size_t)t * NG * NX;
            aHi = g_xm_hi + off; aLo = g_xm_lo + off; astr = NX; ak = (i - 16) * 64;
        }
        const int bk = i * 64;
#pragma unroll
        for (int s = 0; s < 4; ++s) {
            const int row = prow + s * 32;
            const uint32_t soff = SWZ(row * 128 + pseg * 16);
            cp16(stb + soff,          aHi + (size_t)(m0 + row) * astr + ak + pseg * 8);
            cp16(stb + 16384 + soff,  aLo + (size_t)(m0 + row) * astr + ak + pseg * 8);
            cp16(stb + 32768 + soff,  g_Wp_hi + (size_t)(n0g + row) * KTOT + bk + pseg * 8);
            cp16(stb + 49152 + soff,  g_Wp_lo + (size_t)(n0g + row) * KTOT + bk + pseg * 8);
        }
        cp_commit();
    };

    prefetch(0, 0);

    const int mw = (w & 3) * 32;               // warp m-offset in CTA tile
    const int nw = (w >> 2) * 64;              // warp n-offset
    const int lrow = lane & 15;
    const int lcol16 = (lane >> 4) * 16;       // byte offset of k-half

    for (int i = 0; i < NCHUNK; ++i) {
        const int stage = i & 1;
        if (i + 1 < NCHUNK) { prefetch(i + 1, stage ^ 1); cp_wait<1>(); }
        else cp_wait<0>();
        __syncthreads();

        const uint32_t stb = sbase + stage * STAGE_BYTES;
#pragma unroll
        for (int ks = 0; ks < 4; ++ks) {        // K=16 per mma, 4 per 64-chunk
            const int kb = ks * 32;             // byte offset
            uint32_t ah[2][4], bh[4][4];
#pragma unroll
            for (int im = 0; im < 2; ++im)
                ldm4(ah[im], stb + SWZ((mw + im * 16 + lrow) * 128 + kb + lcol16));
#pragma unroll
            for (int jb = 0; jb < 4; ++jb)
                ldm4(bh[jb], stb + 32768 + SWZ((nw + jb * 16 + lrow) * 128 + kb + lcol16));
#pragma unroll
            for (int im = 0; im < 2; ++im)
#pragma unroll
                for (int jn = 0; jn < 8; ++jn)
                    mma_bf16(acc[im][jn], ah[im], bh[jn >> 1][jn & 1], bh[jn >> 1][(jn & 1) + 2]);

            uint32_t bl[4][4];
#pragma unroll
            for (int jb = 0; jb < 4; ++jb)
                ldm4(bl[jb], stb + 49152 + SWZ((nw + jb * 16 + lrow) * 128 + kb + lcol16));
#pragma unroll
            for (int im = 0; im < 2; ++im)
#pragma unroll
                for (int jn = 0; jn < 8; ++jn)
                    mma_bf16(acc[im][jn], ah[im], bl[jn >> 1][jn & 1], bl[jn >> 1][(jn & 1) + 2]);

            uint32_t al[2][4];
#pragma unroll
            for (int im = 0; im < 2; ++im)
                ldm4(al[im], stb + 16384 + SWZ((mw + im * 16 + lrow) * 128 + kb + lcol16));
#pragma unroll
            for (int im = 0; im < 2; ++im)
#pragma unroll
                for (int jn = 0; jn < 8; ++jn)
                    mma_bf16(acc[im][jn], al[im], bh[jn >> 1][jn & 1], bh[jn >> 1][(jn & 1) + 2]);
        }
        __syncthreads();
    }

    // ---- fused cell epilogue ----
    // N layout: n = col_local*4 + gate. Within a quad, bit0 lane pairs hold
    // (i,f) vs (g,o) for the same (batch,col); exchange via shfl_xor(1).
    float* hs_t = g_hs + (size_t)t * NGHH;
    const int odd = lane & 1;
#pragma unroll
    for (int im = 0; im < 2; ++im) {
        const int b = m0 + mw + im * 16 + (lane >> 2) + (odd ? 8 : 0);
#pragma unroll
        for (int jn = 0; jn < 8; ++jn) {
            float c0 = acc[im][jn][0], c1 = acc[im][jn][1];
            float c2 = acc[im][jn][2], c3 = acc[im][jn][3];
            float x0 = __shfl_xor_sync(0xFFFFFFFFu, odd ? c0 : c2, 1);
            float x1 = __shfl_xor_sync(0xFFFFFFFFu, odd ? c1 : c3, 1);
            float iv = odd ? x0 : c0;
            float fv = odd ? x1 : c1;
            float gv = odd ? c2 : x0;
            float ov = odd ? c3 : x1;
            const int col = cgrp * 32 + (w >> 2) * 16 + jn * 2 + ((lane >> 1) & 1);
            float4 bb = g_biasp[col];
            float i_ = sigmoidf_(iv + bb.x);
            float f_ = sigmoidf_(fv + bb.y);
            float g_ = tanhf(gv + bb.z);
            float o_ = sigmoidf_(ov + bb.w);
            const size_t idx = (size_t)b * HH + col;
            float cn = f_ * g_c[idx] + i_ * g_;
            float h = o_ * tanhf(cn);
            g_c[idx] = cn;
            hs_t[idx] = h;
            __nv_bfloat16 hi = __float2bfloat16(h);
            __nv_bfloat16 lo = __float2bfloat16(h - __bfloat162float(hi));
            g_h_hi[wbuf][idx] = hi;
            g_h_lo[wbuf][idx] = lo;
        }
    }
}

// ---------------- output projection ----------------
__global__ void out_kernel(const float* __restrict__ W_lin,
                           const float* __restrict__ b_lin,
                           float* __restrict__ out) {
    const int warp = (blockIdx.x * blockDim.x + threadIdx.x) >> 5;
    const int lane = threadIdx.x & 31;
    if (warp >= NT * NG) return;
    const float* hrow = g_hs + (size_t)warp * HH;
    float s = 0.0f;
#pragma unroll 8
    for (int j = lane; j < HH; j += 32)
        s += hrow[j] * W_lin[j];
#pragma unroll
    for (int o = 16; o; o >>= 1)
        s += __shfl_xor_sync(0xFFFFFFFFu, s, o);
    if (lane == 0) out[warp] = s + b_lin[0];
}

// ---------------- host ----------------
extern "C" void kernel_launch(void* const* d_in, const int* in_sizes, int n_in,
                              void* d_out, int out_size) {
    const float* x     = (const float*)d_in[0];
    const float* maskX = (const float*)d_in[1];
    const float* W_ih  = (const float*)d_in[2];
    const float* W_hh  = (const float*)d_in[3];
    const float* b_ih  = (const float*)d_in[4];
    const float* b_hh  = (const float*)d_in[5];
    const float* W_lin = (const float*)d_in[6];
    const float* b_lin = (const float*)d_in[7];
    float* out = (float*)d_out;

    cudaFuncSetAttribute(lstm_step_kernel,
                         cudaFuncAttributeMaxDynamicSharedMemorySize, DSMEM_BYTES);

    zero_kernel<<<(NGHH + 255) / 256, 256>>>();
    prep_bias_kernel<<<(HH + 255) / 256, 256>>>(b_ih, b_hh);
    prep_W_kernel<<<dim3((KTOT + 255) / 256, G4), 256>>>(W_ih, W_hh);
    prep_xm_kernel<<<dim3((NG * NX) / 256, NT), 256>>>(x, maskX);

    for (int t = 0; t < NT; ++t)
        lstm_step_kernel<<<128, 256, DSMEM_BYTES>>>(t);

    out_kernel<<<(NT * NG + 7) / 8, 256>>>(W_lin, b_lin, out);
}

// round 6
// speedup vs baseline: 2.5044x; 1.2015x over previous
#include <cuda_runtime.h>
#include <cuda_fp16.h>
#include <stdint.h>
#include <math.h>

#define NT 365
#define NG 512
#define NX 256
#define HH 1024
#define KTOT 1280
#define G4 4096
#define NGHH (NG * HH)
#define NCHUNK 20                    // 16 chunks of h (K=1024) + 4 of xm (K=256), 64 each
#define STAGE_BYTES 49152            // A(16KB) + Bhi(16KB) + Blo(16KB)
#define NSTAGE 3
#define DSMEM_BYTES (NSTAGE * STAGE_BYTES)

// ---------------- scratch (__device__ globals; no allocation) ----------------
__device__ float g_c[NGHH];
__device__ float g_hs[(size_t)NT * NGHH];
__device__ __half g_h[2][NGHH];                     // ping-pong, fp16 hi only
__device__ __half g_Wp_hi[(size_t)G4 * KTOT];       // rows permuted: r' = col*4 + gate
__device__ __half g_Wp_lo[(size_t)G4 * KTOT];
__device__ __half g_xm[(size_t)NT * NG * NX];       // fp16 hi only
__device__ float4 g_biasp[HH];                      // per col: (bi, bf, bg, bo)

// ---------------- PTX helpers ----------------
static __device__ __forceinline__ uint32_t smem_u32(const void* p) {
    uint32_t a;
    asm("{ .reg .u64 t; cvta.to.shared.u64 t, %1; cvt.u32.u64 %0, t; }" : "=r"(a) : "l"(p));
    return a;
}
#define SWZ(o) ((o) ^ (((o) >> 3) & 0x70))

static __device__ __forceinline__ void cp16(uint32_t dst, const void* src) {
    asm volatile("cp.async.cg.shared.global [%0], [%1], 16;" :: "r"(dst), "l"(src));
}
static __device__ __forceinline__ void cp_commit() {
    asm volatile("cp.async.commit_group;" ::: "memory");
}
template <int N>
static __device__ __forceinline__ void cp_wait() {
    asm volatile("cp.async.wait_group %0;" :: "n"(N) : "memory");
}
static __device__ __forceinline__ void ldm4(uint32_t* r, uint32_t addr) {
    asm volatile("ldmatrix.sync.aligned.m8n8.x4.shared.b16 {%0,%1,%2,%3}, [%4];"
                 : "=r"(r[0]), "=r"(r[1]), "=r"(r[2]), "=r"(r[3]) : "r"(addr));
}
static __device__ __forceinline__ void mma_f16(float* d, const uint32_t* a,
                                               uint32_t b0, uint32_t b1) {
    asm volatile(
        "mma.sync.aligned.m16n8k16.row.col.f32.f16.f16.f32 "
        "{%0,%1,%2,%3}, {%4,%5,%6,%7}, {%8,%9}, {%0,%1,%2,%3};"
        : "+f"(d[0]), "+f"(d[1]), "+f"(d[2]), "+f"(d[3])
        : "r"(a[0]), "r"(a[1]), "r"(a[2]), "r"(a[3]), "r"(b0), "r"(b1));
}
static __device__ __forceinline__ float sigf(float x) {
    return __fdividef(1.0f, 1.0f + __expf(-x));
}
static __device__ __forceinline__ float tanh_fast(float x) {
    return 2.0f * sigf(2.0f * x) - 1.0f;
}

// ---------------- prep kernels ----------------
__global__ void zero_kernel() {
    int i = blockIdx.x * 256 + threadIdx.x;
    if (i < NGHH) {
        g_c[i] = 0.0f;
        g_h[0][i] = __float2half(0.0f);
    }
}

__global__ void prep_bias_kernel(const float* __restrict__ b_ih, const float* __restrict__ b_hh) {
    int col = blockIdx.x * 256 + threadIdx.x;
    if (col >= HH) return;
    float4 v;
    v.x = b_ih[col] + b_hh[col];
    v.y = b_ih[HH + col] + b_hh[HH + col];
    v.z = b_ih[2 * HH + col] + b_hh[2 * HH + col];
    v.w = b_ih[3 * HH + col] + b_hh[3 * HH + col];
    g_biasp[col] = v;
}

// W' row r' = col*4 + gate; k cols 0..1023 from W_hh, 1024..1279 from W_ih (fused K)
__global__ void prep_W_kernel(const float* __restrict__ W_ih, const float* __restrict__ W_hh) {
    int k = blockIdx.x * 256 + threadIdx.x;
    int r = blockIdx.y;                       // old row: gate*1024 + col
    if (k >= KTOT) return;
    float v = (k < HH) ? W_hh[(size_t)r * HH + k]
                       : W_ih[(size_t)r * NX + (k - HH)];
    __half hi = __float2half(v);
    __half lo = __float2half(v - __half2float(hi));
    int gate = r >> 10, col = r & 1023;
    size_t rp = (size_t)(col * 4 + gate) * KTOT + k;
    g_Wp_hi[rp] = hi;
    g_Wp_lo[rp] = lo;
}

__global__ void prep_xm_kernel(const float* __restrict__ x, const float* __restrict__ maskX) {
    int idx = blockIdx.x * 256 + threadIdx.x;   // 0..NG*NX-1
    int t = blockIdx.y;
    size_t gi = (size_t)t * (NG * NX) + idx;
    g_xm[gi] = __float2half(x[gi] * maskX[idx]);
}

// ---------------- fused step: GEMM (fp16 2-term) + cell epilogue ----------------
// grid 128 = 4 m-groups(128 batch) x 32 col-groups(32 hidden cols x 4 gates = 128 N)
__global__ __launch_bounds__(256, 1) void lstm_step_kernel(int t) {
    extern __shared__ char dsm[];
    const uint32_t sbase = smem_u32(dsm);
    const int tid = threadIdx.x;
    const int w = tid >> 5;
    const int lane = tid & 31;
    const int m0 = (blockIdx.x & 3) * 128;
    const int cgrp = blockIdx.x >> 2;
    const int n0g = cgrp * 128;                 // W' row base (contiguous after permute)
    const int rbuf = t & 1;
    const int wbuf = (t + 1) & 1;

    const int prow = tid >> 3;                  // cp.async: 0..31 (+32*s)
    const int pseg = tid & 7;                   // 16B segment in 128B row

    float acc[2][8][4];
#pragma unroll
    for (int im = 0; im < 2; ++im)
#pragma unroll
        for (int jn = 0; jn < 8; ++jn)
#pragma unroll
            for (int r = 0; r < 4; ++r) acc[im][jn][r] = 0.0f;

    auto prefetch = [&](int i, int stage) {
        const uint32_t stb = sbase + stage * STAGE_BYTES;
        const __half* aSrc;
        int astr, ak;
        if (i < 16) {
            aSrc = g_h[rbuf]; astr = HH; ak = i * 64;
        } else {
            aSrc = g_xm + (size_t)t * NG * NX; astr = NX; ak = (i - 16) * 64;
        }
        const int bk = i * 64;
#pragma unroll
        for (int s = 0; s < 4; ++s) {
            const int row = prow + s * 32;
            const uint32_t soff = SWZ(row * 128 + pseg * 16);
            cp16(stb + soff,          aSrc + (size_t)(m0 + row) * astr + ak + pseg * 8);
            cp16(stb + 16384 + soff,  g_Wp_hi + (size_t)(n0g + row) * KTOT + bk + pseg * 8);
            cp16(stb + 32768 + soff,  g_Wp_lo + (size_t)(n0g + row) * KTOT + bk + pseg * 8);
        }
        cp_commit();
    };

    prefetch(0, 0);
    prefetch(1, 1);

    const int mw = (w & 3) * 32;               // warp m-offset in CTA tile
    const int nw = (w >> 2) * 64;              // warp n-offset
    const int lrow = lane & 15;
    const int lcol16 = (lane >> 4) * 16;       // byte offset of k-half

    int stage = 0;
    for (int i = 0; i < NCHUNK; ++i) {
        if (i + 1 < NCHUNK) cp_wait<1>();      // chunk i data landed (i+1 may be pending)
        else cp_wait<0>();
        __syncthreads();                        // data visible + compute(i-1) finished everywhere
        if (i + 2 < NCHUNK) {
            int ns = stage + 2; if (ns >= NSTAGE) ns -= NSTAGE;
            prefetch(i + 2, ns);               // writes stage (i-1)%3: safe after barrier
        }

        const uint32_t stb = sbase + stage * STAGE_BYTES;
#pragma unroll
        for (int ks = 0; ks < 4; ++ks) {        // K=16 per mma, 4 per 64-chunk
            const int kb = ks * 32;             // byte offset
            uint32_t ah[2][4], bh[4][4];
#pragma unroll
            for (int im = 0; im < 2; ++im)
                ldm4(ah[im], stb + SWZ((mw + im * 16 + lrow) * 128 + kb + lcol16));
#pragma unroll
            for (int jb = 0; jb < 4; ++jb)
                ldm4(bh[jb], stb + 16384 + SWZ((nw + jb * 16 + lrow) * 128 + kb + lcol16));
#pragma unroll
            for (int im = 0; im < 2; ++im)
#pragma unroll
                for (int jn = 0; jn < 8; ++jn)
                    mma_f16(acc[im][jn], ah[im], bh[jn >> 1][jn & 1], bh[jn >> 1][(jn & 1) + 2]);

            uint32_t bl[4][4];
#pragma unroll
            for (int jb = 0; jb < 4; ++jb)
                ldm4(bl[jb], stb + 32768 + SWZ((nw + jb * 16 + lrow) * 128 + kb + lcol16));
#pragma unroll
            for (int im = 0; im < 2; ++im)
#pragma unroll
                for (int jn = 0; jn < 8; ++jn)
                    mma_f16(acc[im][jn], ah[im], bl[jn >> 1][jn & 1], bl[jn >> 1][(jn & 1) + 2]);
        }
        ++stage; if (stage >= NSTAGE) stage = 0;
    }

    // ---- fused cell epilogue ----
    // N layout: n = col_local*4 + gate. Within a quad, bit0 lane pairs hold
    // (i,f) vs (g,o) for the same (batch,col); exchange via shfl_xor(1).
    float* hs_t = g_hs + (size_t)t * NGHH;
    const int odd = lane & 1;
#pragma unroll
    for (int im = 0; im < 2; ++im) {
        const int b = m0 + mw + im * 16 + (lane >> 2) + (odd ? 8 : 0);
#pragma unroll
        for (int jn = 0; jn < 8; ++jn) {
            float c0 = acc[im][jn][0], c1 = acc[im][jn][1];
            float c2 = acc[im][jn][2], c3 = acc[im][jn][3];
            float x0 = __shfl_xor_sync(0xFFFFFFFFu, odd ? c0 : c2, 1);
            float x1 = __shfl_xor_sync(0xFFFFFFFFu, odd ? c1 : c3, 1);
            float iv = odd ? x0 : c0;
            float fv = odd ? x1 : c1;
            float gv = odd ? c2 : x0;
            float ov = odd ? c3 : x1;
            const int col = cgrp * 32 + (w >> 2) * 16 + jn * 2 + ((lane >> 1) & 1);
            float4 bb = g_biasp[col];
            float i_ = sigf(iv + bb.x);
            float f_ = sigf(fv + bb.y);
            float g_ = tanh_fast(gv + bb.z);
            float o_ = sigf(ov + bb.w);
            const size_t idx = (size_t)b * HH + col;
            float cn = f_ * g_c[idx] + i_ * g_;
            float h = o_ * tanh_fast(cn);
            g_c[idx] = cn;
            hs_t[idx] = h;
            g_h[wbuf][idx] = __float2half(h);
        }
    }
}

// ---------------- output projection ----------------
__global__ void out_kernel(const float* __restrict__ W_lin,
                           const float* __restrict__ b_lin,
                           float* __restrict__ out) {
    const int warp = (blockIdx.x * blockDim.x + threadIdx.x) >> 5;
    const int lane = threadIdx.x & 31;
    if (warp >= NT * NG) return;
    const float* hrow = g_hs + (size_t)warp * HH;
    float s = 0.0f;
#pragma unroll 8
    for (int j = lane; j < HH; j += 32)
        s += hrow[j] * W_lin[j];
#pragma unroll
    for (int o = 16; o; o >>= 1)
        s += __shfl_xor_sync(0xFFFFFFFFu, s, o);
    if (lane == 0) out[warp] = s + b_lin[0];
}

// ---------------- host ----------------
extern "C" void kernel_launch(void* const* d_in, const int* in_sizes, int n_in,
                              void* d_out, int out_size) {
    const float* x     = (const float*)d_in[0];
    const float* maskX = (const float*)d_in[1];
    const float* W_ih  = (const float*)d_in[2];
    const float* W_hh  = (const float*)d_in[3];
    const float* b_ih  = (const float*)d_in[4];
    const float* b_hh  = (const float*)d_in[5];
    const float* W_lin = (const float*)d_in[6];
    const float* b_lin = (const float*)d_in[7];
    float* out = (float*)d_out;

    cudaFuncSetAttribute(lstm_step_kernel,
                         cudaFuncAttributeMaxDynamicSharedMemorySize, DSMEM_BYTES);

    zero_kernel<<<(NGHH + 255) / 256, 256>>>();
    prep_bias_kernel<<<(HH + 255) / 256, 256>>>(b_ih, b_hh);
    prep_W_kernel<<<dim3((KTOT + 255) / 256, G4), 256>>>(W_ih, W_hh);
    prep_xm_kernel<<<dim3((NG * NX) / 256, NT), 256>>>(x, maskX);

    for (int t = 0; t < NT; ++t)
        lstm_step_kernel<<<128, 256, DSMEM_BYTES>>>(t);

    out_kernel<<<(NT * NG + 7) / 8, 256>>>(W_lin, b_lin, out);
}

// round 7
// speedup vs baseline: 3.7748x; 1.5073x over previous
#include <cuda_runtime.h>
#include <cuda_fp16.h>
#include <stdint.h>
#include <math.h>

#define NT 365
#define NG 512
#define NX 256
#define HH 1024
#define KTOT 1280
#define G4 4096
#define NGHH (NG * HH)
#define NCHUNK 20                    // 16 chunks of h (K=1024) + 4 of xm (K=256), 64 each
#define STAGE_BYTES 49152            // A(16KB) + Bhi(16KB) + Blo(16KB)
#define NSTAGE 3
#define DSMEM_BYTES (NSTAGE * STAGE_BYTES)

// ---------------- scratch (__device__ globals; no allocation) ----------------
__device__ float g_c[NGHH];
__device__ float g_hs[(size_t)NT * NGHH];
__device__ __half g_h[2][NGHH];                     // ping-pong, fp16
__device__ __half g_Wp_hi[(size_t)G4 * KTOT];       // rows permuted: r' = col*4 + gate
__device__ __half g_Wp_lo[(size_t)G4 * KTOT];
__device__ __half g_xm[(size_t)NT * NG * NX];       // fp16
__device__ float4 g_biasp[HH];                      // per col: (bi, bf, bg, bo)

// ---------------- PTX helpers ----------------
static __device__ __forceinline__ uint32_t smem_u32(const void* p) {
    uint32_t a;
    asm("{ .reg .u64 t; cvta.to.shared.u64 t, %1; cvt.u32.u64 %0, t; }" : "=r"(a) : "l"(p));
    return a;
}
#define SWZ(o) ((o) ^ (((o) >> 3) & 0x70))

static __device__ __forceinline__ void cp16(uint32_t dst, const void* src) {
    asm volatile("cp.async.cg.shared.global [%0], [%1], 16;" :: "r"(dst), "l"(src));
}
static __device__ __forceinline__ void cp_commit() {
    asm volatile("cp.async.commit_group;" ::: "memory");
}
template <int N>
static __device__ __forceinline__ void cp_wait() {
    asm volatile("cp.async.wait_group %0;" :: "n"(N) : "memory");
}
static __device__ __forceinline__ void ldm4(uint32_t* r, uint32_t addr) {
    asm volatile("ldmatrix.sync.aligned.m8n8.x4.shared.b16 {%0,%1,%2,%3}, [%4];"
                 : "=r"(r[0]), "=r"(r[1]), "=r"(r[2]), "=r"(r[3]) : "r"(addr));
}
static __device__ __forceinline__ void mma_f16(float* d, const uint32_t* a,
                                               uint32_t b0, uint32_t b1) {
    asm volatile(
        "mma.sync.aligned.m16n8k16.row.col.f32.f16.f16.f32 "
        "{%0,%1,%2,%3}, {%4,%5,%6,%7}, {%8,%9}, {%0,%1,%2,%3};"
        : "+f"(d[0]), "+f"(d[1]), "+f"(d[2]), "+f"(d[3])
        : "r"(a[0]), "r"(a[1]), "r"(a[2]), "r"(a[3]), "r"(b0), "r"(b1));
}
static __device__ __forceinline__ float tanh_ap(float x) {
    float y;
    asm("tanh.approx.f32 %0, %1;" : "=f"(y) : "f"(x));
    return y;
}
static __device__ __forceinline__ float sig_ap(float x) {
    return fmaf(tanh_ap(0.5f * x), 0.5f, 0.5f);
}

// ---------------- prep kernels ----------------
__global__ void zero_kernel() {
    int i = blockIdx.x * 256 + threadIdx.x;
    if (i < NGHH) {
        g_c[i] = 0.0f;
        g_h[0][i] = __float2half(0.0f);
    }
}

__global__ void prep_bias_kernel(const float* __restrict__ b_ih, const float* __restrict__ b_hh) {
    int col = blockIdx.x * 256 + threadIdx.x;
    if (col >= HH) return;
    float4 v;
    v.x = b_ih[col] + b_hh[col];
    v.y = b_ih[HH + col] + b_hh[HH + col];
    v.z = b_ih[2 * HH + col] + b_hh[2 * HH + col];
    v.w = b_ih[3 * HH + col] + b_hh[3 * HH + col];
    g_biasp[col] = v;
}

// W' row r' = col*4 + gate; k cols 0..1023 from W_hh, 1024..1279 from W_ih (fused K)
__global__ void prep_W_kernel(const float* __restrict__ W_ih, const float* __restrict__ W_hh) {
    int k = blockIdx.x * 256 + threadIdx.x;
    int r = blockIdx.y;                       // old row: gate*1024 + col
    if (k >= KTOT) return;
    float v = (k < HH) ? W_hh[(size_t)r * HH + k]
                       : W_ih[(size_t)r * NX + (k - HH)];
    __half hi = __float2half(v);
    __half lo = __float2half(v - __half2float(hi));
    int gate = r >> 10, col = r & 1023;
    size_t rp = (size_t)(col * 4 + gate) * KTOT + k;
    g_Wp_hi[rp] = hi;
    g_Wp_lo[rp] = lo;
}

__global__ void prep_xm_kernel(const float* __restrict__ x, const float* __restrict__ maskX) {
    int idx = blockIdx.x * 256 + threadIdx.x;   // 0..NG*NX-1
    int t = blockIdx.y;
    size_t gi = (size_t)t * (NG * NX) + idx;
    g_xm[gi] = __float2half(x[gi] * maskX[idx]);
}

// ---------------- fused step: GEMM (fp16 2-term) + cell epilogue ----------------
// grid 128 = 4 m-groups(128 batch) x 32 col-groups(32 hidden cols x 4 gates = 128 N)
__global__ __launch_bounds__(256, 1) void lstm_step_kernel(int t) {
    extern __shared__ char dsm[];
    const uint32_t sbase = smem_u32(dsm);
    const int tid = threadIdx.x;
    const int w = tid >> 5;
    const int lane = tid & 31;
    const int m0 = (blockIdx.x & 3) * 128;
    const int cgrp = blockIdx.x >> 2;
    const int n0g = cgrp * 128;                 // W' row base (contiguous after permute)
    const int rbuf = t & 1;
    const int wbuf = (t + 1) & 1;

    const int prow = tid >> 3;                  // cp.async: 0..31 (+32*s)
    const int pseg = tid & 7;                   // 16B segment in 128B row

    float acc[2][8][4];
#pragma unroll
    for (int im = 0; im < 2; ++im)
#pragma unroll
        for (int jn = 0; jn < 8; ++jn)
#pragma unroll
            for (int r = 0; r < 4; ++r) acc[im][jn][r] = 0.0f;

    auto prefetch = [&](int i, int stage) {
        const uint32_t stb = sbase + stage * STAGE_BYTES;
        const __half* aSrc;
        int astr, ak;
        if (i < 16) {
            aSrc = g_h[rbuf]; astr = HH; ak = i * 64;
        } else {
            aSrc = g_xm + (size_t)t * NG * NX; astr = NX; ak = (i - 16) * 64;
        }
        const int bk = i * 64;
#pragma unroll
        for (int s = 0; s < 4; ++s) {
            const int row = prow + s * 32;
            const uint32_t soff = SWZ(row * 128 + pseg * 16);
            cp16(stb + soff,          aSrc + (size_t)(m0 + row) * astr + ak + pseg * 8);
            cp16(stb + 16384 + soff,  g_Wp_hi + (size_t)(n0g + row) * KTOT + bk + pseg * 8);
            cp16(stb + 32768 + soff,  g_Wp_lo + (size_t)(n0g + row) * KTOT + bk + pseg * 8);
        }
        cp_commit();
    };

    prefetch(0, 0);
    prefetch(1, 1);

    const int mw = (w & 3) * 32;               // warp m-offset in CTA tile
    const int nw = (w >> 2) * 64;              // warp n-offset
    const int lrow = lane & 15;
    const int lcol16 = (lane >> 4) * 16;       // byte offset of k-half

    int stage = 0;
    for (int i = 0; i < NCHUNK; ++i) {
        if (i + 1 < NCHUNK) cp_wait<1>();      // chunk i data landed (i+1 may be pending)
        else cp_wait<0>();
        __syncthreads();                        // data visible + compute(i-1) done everywhere
        if (i + 2 < NCHUNK) {
            int ns = stage + 2; if (ns >= NSTAGE) ns -= NSTAGE;
            prefetch(i + 2, ns);               // writes stage (i-1)%3: safe after barrier
        }

        const uint32_t stb = sbase + stage * STAGE_BYTES;
#pragma unroll
        for (int ks = 0; ks < 4; ++ks) {        // K=16 per mma, 4 per 64-chunk
            const int kb = ks * 32;             // byte offset
            uint32_t ah[2][4], bh[4][4];
#pragma unroll
            for (int im = 0; im < 2; ++im)
                ldm4(ah[im], stb + SWZ((mw + im * 16 + lrow) * 128 + kb + lcol16));
#pragma unroll
            for (int jb = 0; jb < 4; ++jb)
                ldm4(bh[jb], stb + 16384 + SWZ((nw + jb * 16 + lrow) * 128 + kb + lcol16));
#pragma unroll
            for (int im = 0; im < 2; ++im)
#pragma unroll
                for (int jn = 0; jn < 8; ++jn)
                    mma_f16(acc[im][jn], ah[im], bh[jn >> 1][jn & 1], bh[jn >> 1][(jn & 1) + 2]);

            uint32_t bl[4][4];
#pragma unroll
            for (int jb = 0; jb < 4; ++jb)
                ldm4(bl[jb], stb + 32768 + SWZ((nw + jb * 16 + lrow) * 128 + kb + lcol16));
#pragma unroll
            for (int im = 0; im < 2; ++im)
#pragma unroll
                for (int jn = 0; jn < 8; ++jn)
                    mma_f16(acc[im][jn], ah[im], bl[jn >> 1][jn & 1], bl[jn >> 1][(jn & 1) + 2]);
        }
        ++stage; if (stage >= NSTAGE) stage = 0;
    }

    // ---- epilogue: fragments -> smem (transpose) -> coalesced cell update ----
    // sT[row][n'] with n' = col_local*4 + gate, row stride 132 floats.
    float* sT = (float*)dsm;
    __syncthreads();                            // last stage reads done before overwrite
#pragma unroll
    for (int im = 0; im < 2; ++im) {
        const int r0 = mw + im * 16 + (lane >> 2);
#pragma unroll
        for (int jn = 0; jn < 8; ++jn) {
            const int nb = nw + jn * 8 + (lane & 3) * 2;
            *(float2*)&sT[r0 * 132 + nb]       = make_float2(acc[im][jn][0], acc[im][jn][1]);
            *(float2*)&sT[(r0 + 8) * 132 + nb] = make_float2(acc[im][jn][2], acc[im][jn][3]);
        }
    }
    __syncthreads();

    // 16 threads cover 32 contiguous cols of one row -> 128B-coalesced global access
    float* hs_t = g_hs + (size_t)t * NGHH;
    const int tg = tid & 15;                   // col-pair group (2 cols = 8 n')
    const int rr = tid >> 4;                   // 0..15
#pragma unroll
    for (int p = 0; p < 8; ++p) {
        const int row = p * 16 + rr;
        const int b = m0 + row;
        const float4 gA = *(float4*)&sT[row * 132 + tg * 8];      // gates of col0
        const float4 gB = *(float4*)&sT[row * 132 + tg * 8 + 4];  // gates of col1
        const int col = cgrp * 32 + tg * 2;
        const float4 bb0 = g_biasp[col];
        const float4 bb1 = g_biasp[col + 1];
        const size_t idx = (size_t)b * HH + col;
        const float2 cc = *(float2*)&g_c[idx];

        float i0 = sig_ap(gA.x + bb0.x);
        float f0 = sig_ap(gA.y + bb0.y);
        float q0 = tanh_ap(gA.z + bb0.z);
        float o0 = sig_ap(gA.w + bb0.w);
        float i1 = sig_ap(gB.x + bb1.x);
        float f1 = sig_ap(gB.y + bb1.y);
        float q1 = tanh_ap(gB.z + bb1.z);
        float o1 = sig_ap(gB.w + bb1.w);

        float cn0 = f0 * cc.x + i0 * q0;
        float cn1 = f1 * cc.y + i1 * q1;
        float h0 = o0 * tanh_ap(cn0);
        float h1 = o1 * tanh_ap(cn1);

        *(float2*)&g_c[idx] = make_float2(cn0, cn1);
        *(float2*)&hs_t[idx] = make_float2(h0, h1);
        *(__half2*)&g_h[wbuf][idx] = __floats2half2_rn(h0, h1);
    }
}

// ---------------- output projection ----------------
__global__ void out_kernel(const float* __restrict__ W_lin,
                           const float* __restrict__ b_lin,
                           float* __restrict__ out) {
    const int warp = (blockIdx.x * blockDim.x + threadIdx.x) >> 5;
    const int lane = threadIdx.x & 31;
    if (warp >= NT * NG) return;
    const float* hrow = g_hs + (size_t)warp * HH;
    float s = 0.0f;
#pragma unroll 8
    for (int j = lane; j < HH; j += 32)
        s += hrow[j] * W_lin[j];
#pragma unroll
    for (int o = 16; o; o >>= 1)
        s += __shfl_xor_sync(0xFFFFFFFFu, s, o);
    if (lane == 0) out[warp] = s + b_lin[0];
}

// ---------------- host ----------------
extern "C" void kernel_launch(void* const* d_in, const int* in_sizes, int n_in,
                              void* d_out, int out_size) {
    const float* x     = (const float*)d_in[0];
    const float* maskX = (const float*)d_in[1];
    const float* W_ih  = (const float*)d_in[2];
    const float* W_hh  = (const float*)d_in[3];
    const float* b_ih  = (const float*)d_in[4];
    const float* b_hh  = (const float*)d_in[5];
    const float* W_lin = (const float*)d_in[6];
    const float* b_lin = (const float*)d_in[7];
    float* out = (float*)d_out;

    cudaFuncSetAttribute(lstm_step_kernel,
                         cudaFuncAttributeMaxDynamicSharedMemorySize, DSMEM_BYTES);

    zero_kernel<<<(NGHH + 255) / 256, 256>>>();
    prep_bias_kernel<<<(HH + 255) / 256, 256>>>(b_ih, b_hh);
    prep_W_kernel<<<dim3((KTOT + 255) / 256, G4), 256>>>(W_ih, W_hh);
    prep_xm_kernel<<<dim3((NG * NX) / 256, NT), 256>>>(x, maskX);

    for (int t = 0; t < NT; ++t)
        lstm_step_kernel<<<128, 256, DSMEM_BYTES>>>(t);

    out_kernel<<<(NT * NG + 7) / 8, 256>>>(W_lin, b_lin, out);
}

// round 8
// speedup vs baseline: 5.7621x; 1.5264x over previous
#include <cuda_runtime.h>
#include <cuda_fp16.h>
#include <stdint.h>
#include <math.h>

#define NT 365
#define NG 512
#define NX 256
#define HH 1024
#define KTOT 1280
#define G4 4096
#define NGHH (NG * HH)
#define NCHUNK 20                    // 16 chunks of h (K=1024) + 4 of xm (K=256), 64 each
#define STAGE_BYTES 32768            // A(16KB) + B(16KB)
#define NSTAGE 3
#define DSMEM_BYTES (NSTAGE * STAGE_BYTES)
#define NBLK 128

// ---------------- scratch (__device__ globals; no allocation) ----------------
__device__ float g_c[NGHH];
__device__ float g_hs[(size_t)NT * NGHH];
__device__ __half g_h[2][NGHH];                     // ping-pong, fp16
__device__ __half g_Wp[(size_t)G4 * KTOT];          // rows permuted: r' = col*4 + gate
__device__ __half g_xm[(size_t)NT * NG * NX];       // fp16
__device__ float4 g_biasp[HH];                      // per col: (bi, bf, bg, bo)
__device__ unsigned int g_bar_count;
__device__ volatile unsigned int g_bar_gen;

// ---------------- PTX helpers ----------------
static __device__ __forceinline__ uint32_t smem_u32(const void* p) {
    uint32_t a;
    asm("{ .reg .u64 t; cvta.to.shared.u64 t, %1; cvt.u32.u64 %0, t; }" : "=r"(a) : "l"(p));
    return a;
}
#define SWZ(o) ((o) ^ (((o) >> 3) & 0x70))

static __device__ __forceinline__ void cp16(uint32_t dst, const void* src) {
    asm volatile("cp.async.cg.shared.global [%0], [%1], 16;" :: "r"(dst), "l"(src));
}
static __device__ __forceinline__ void cp_commit() {
    asm volatile("cp.async.commit_group;" ::: "memory");
}
template <int N>
static __device__ __forceinline__ void cp_wait() {
    asm volatile("cp.async.wait_group %0;" :: "n"(N) : "memory");
}
static __device__ __forceinline__ void ldm4(uint32_t* r, uint32_t addr) {
    asm volatile("ldmatrix.sync.aligned.m8n8.x4.shared.b16 {%0,%1,%2,%3}, [%4];"
                 : "=r"(r[0]), "=r"(r[1]), "=r"(r[2]), "=r"(r[3]) : "r"(addr));
}
static __device__ __forceinline__ void mma_f16(float* d, const uint32_t* a,
                                               uint32_t b0, uint32_t b1) {
    asm volatile(
        "mma.sync.aligned.m16n8k16.row.col.f32.f16.f16.f32 "
        "{%0,%1,%2,%3}, {%4,%5,%6,%7}, {%8,%9}, {%0,%1,%2,%3};"
        : "+f"(d[0]), "+f"(d[1]), "+f"(d[2]), "+f"(d[3])
        : "r"(a[0]), "r"(a[1]), "r"(a[2]), "r"(a[3]), "r"(b0), "r"(b1));
}
static __device__ __forceinline__ float tanh_ap(float x) {
    float y;
    asm("tanh.approx.f32 %0, %1;" : "=f"(y) : "f"(x));
    return y;
}
static __device__ __forceinline__ float sig_ap(float x) {
    return fmaf(tanh_ap(0.5f * x), 0.5f, 0.5f);
}

// software grid barrier (all NBLK CTAs resident: 128 <= 148 SMs)
static __device__ __forceinline__ void grid_sync() {
    __syncthreads();
    if (threadIdx.x == 0) {
        unsigned int gen = g_bar_gen;
        __threadfence();
        unsigned int arrived = atomicAdd(&g_bar_count, 1u);
        if (arrived == NBLK - 1) {
            g_bar_count = 0;
            __threadfence();
            g_bar_gen = gen + 1;
        } else {
            while (g_bar_gen == gen) { }
            __threadfence();
        }
    }
    __syncthreads();
}

// ---------------- prep kernels ----------------
__global__ void zero_kernel() {
    int i = blockIdx.x * 256 + threadIdx.x;
    if (i < NGHH) {
        g_c[i] = 0.0f;
        g_h[0][i] = __float2half(0.0f);
    }
    if (i == 0) { g_bar_count = 0; g_bar_gen = 0; }
}

__global__ void prep_bias_kernel(const float* __restrict__ b_ih, const float* __restrict__ b_hh) {
    int col = blockIdx.x * 256 + threadIdx.x;
    if (col >= HH) return;
    float4 v;
    v.x = b_ih[col] + b_hh[col];
    v.y = b_ih[HH + col] + b_hh[HH + col];
    v.z = b_ih[2 * HH + col] + b_hh[2 * HH + col];
    v.w = b_ih[3 * HH + col] + b_hh[3 * HH + col];
    g_biasp[col] = v;
}

// W' row r' = col*4 + gate; k cols 0..1023 from W_hh, 1024..1279 from W_ih (fused K)
__global__ void prep_W_kernel(const float* __restrict__ W_ih, const float* __restrict__ W_hh) {
    int k = blockIdx.x * 256 + threadIdx.x;
    int r = blockIdx.y;                       // old row: gate*1024 + col
    if (k >= KTOT) return;
    float v = (k < HH) ? W_hh[(size_t)r * HH + k]
                       : W_ih[(size_t)r * NX + (k - HH)];
    int gate = r >> 10, col = r & 1023;
    g_Wp[(size_t)(col * 4 + gate) * KTOT + k] = __float2half(v);
}

__global__ void prep_xm_kernel(const float* __restrict__ x, const float* __restrict__ maskX) {
    int idx = blockIdx.x * 256 + threadIdx.x;   // 0..NG*NX-1
    int t = blockIdx.y;
    size_t gi = (size_t)t * (NG * NX) + idx;
    g_xm[gi] = __float2half(x[gi] * maskX[idx]);
}

// ---------------- persistent fused LSTM: all 365 steps in one kernel ----------------
// grid 128 = 4 m-groups(128 batch) x 32 col-groups(32 hidden cols x 4 gates = 128 N)
__global__ __launch_bounds__(256, 1) void lstm_persist_kernel() {
    extern __shared__ char dsm[];
    const uint32_t sbase = smem_u32(dsm);
    const int tid = threadIdx.x;
    const int w = tid >> 5;
    const int lane = tid & 31;
    const int m0 = (blockIdx.x & 3) * 128;
    const int cgrp = blockIdx.x >> 2;
    const int n0g = cgrp * 128;                 // W' row base (contiguous after permute)

    const int prow = tid >> 3;                  // cp.async: 0..31 (+32*s)
    const int pseg = tid & 7;                   // 16B segment in 128B row

    const int mw = (w & 3) * 32;                // warp m-offset
    const int nw = (w >> 2) * 64;               // warp n-offset
    const int lrow = lane & 15;
    const int lcol16 = (lane >> 4) * 16;        // byte offset of k-half

    const int tg = tid & 15;                    // epilogue col-pair group
    const int rr = tid >> 4;                    // epilogue row group

#pragma unroll 1
    for (int t = 0; t < NT; ++t) {
        const int rbuf = t & 1;
        const int wbuf = (t + 1) & 1;

        float acc[2][8][4];
#pragma unroll
        for (int im = 0; im < 2; ++im)
#pragma unroll
            for (int jn = 0; jn < 8; ++jn)
#pragma unroll
                for (int r = 0; r < 4; ++r) acc[im][jn][r] = 0.0f;

        auto prefetch = [&](int i, int stage) {
            const uint32_t stb = sbase + stage * STAGE_BYTES;
            const __half* aSrc;
            int astr, ak;
            if (i < 16) {
                aSrc = g_h[rbuf]; astr = HH; ak = i * 64;
            } else {
                aSrc = g_xm + (size_t)t * NG * NX; astr = NX; ak = (i - 16) * 64;
            }
            const int bk = i * 64;
#pragma unroll
            for (int s = 0; s < 4; ++s) {
                const int row = prow + s * 32;
                const uint32_t soff = SWZ(row * 128 + pseg * 16);
                cp16(stb + soff,         aSrc + (size_t)(m0 + row) * astr + ak + pseg * 8);
                cp16(stb + 16384 + soff, g_Wp + (size_t)(n0g + row) * KTOT + bk + pseg * 8);
            }
            cp_commit();
        };

        prefetch(0, 0);
        prefetch(1, 1);

        int stage = 0;
        for (int i = 0; i < NCHUNK; ++i) {
            if (i + 1 < NCHUNK) cp_wait<1>();   // chunk i landed (i+1 may be pending)
            else cp_wait<0>();
            __syncthreads();                     // data visible + compute(i-1) done
            if (i + 2 < NCHUNK) {
                int ns = stage + 2; if (ns >= NSTAGE) ns -= NSTAGE;
                prefetch(i + 2, ns);            // writes stage (i-1)%3: safe after barrier
            }

            const uint32_t stb = sbase + stage * STAGE_BYTES;
#pragma unroll
            for (int ks = 0; ks < 4; ++ks) {     // K=16 per mma, 4 per 64-chunk
                const int kb = ks * 32;
                uint32_t ah[2][4], bh[4][4];
#pragma unroll
                for (int im = 0; im < 2; ++im)
                    ldm4(ah[im], stb + SWZ((mw + im * 16 + lrow) * 128 + kb + lcol16));
#pragma unroll
                for (int jb = 0; jb < 4; ++jb)
                    ldm4(bh[jb], stb + 16384 + SWZ((nw + jb * 16 + lrow) * 128 + kb + lcol16));
#pragma unroll
                for (int im = 0; im < 2; ++im)
#pragma unroll
                    for (int jn = 0; jn < 8; ++jn)
                        mma_f16(acc[im][jn], ah[im], bh[jn >> 1][jn & 1], bh[jn >> 1][(jn & 1) + 2]);
            }
            ++stage; if (stage >= NSTAGE) stage = 0;
        }

        // ---- epilogue: fragments -> smem (transpose) -> coalesced cell update ----
        float* sT = (float*)dsm;                // 128 x 132 fp32 = 67.6KB < 96KB
        __syncthreads();                        // mainloop smem reads done
#pragma unroll
        for (int im = 0; im < 2; ++im) {
            const int r0 = mw + im * 16 + (lane >> 2);
#pragma unroll
            for (int jn = 0; jn < 8; ++jn) {
                const int nb = nw + jn * 8 + (lane & 3) * 2;
                *(float2*)&sT[r0 * 132 + nb]       = make_float2(acc[im][jn][0], acc[im][jn][1]);
                *(float2*)&sT[(r0 + 8) * 132 + nb] = make_float2(acc[im][jn][2], acc[im][jn][3]);
            }
        }
        __syncthreads();

        float* hs_t = g_hs + (size_t)t * NGHH;
#pragma unroll
        for (int p = 0; p < 8; ++p) {
            const int row = p * 16 + rr;
            const int b = m0 + row;
            const float4 gA = *(float4*)&sT[row * 132 + tg * 8];
            const float4 gB = *(float4*)&sT[row * 132 + tg * 8 + 4];
            const int col = cgrp * 32 + tg * 2;
            const float4 bb0 = g_biasp[col];
            const float4 bb1 = g_biasp[col + 1];
            const size_t idx = (size_t)b * HH + col;
            const float2 cc = *(float2*)&g_c[idx];

            float i0 = sig_ap(gA.x + bb0.x);
            float f0 = sig_ap(gA.y + bb0.y);
            float q0 = tanh_ap(gA.z + bb0.z);
            float o0 = sig_ap(gA.w + bb0.w);
            float i1 = sig_ap(gB.x + bb1.x);
            float f1 = sig_ap(gB.y + bb1.y);
            float q1 = tanh_ap(gB.z + bb1.z);
            float o1 = sig_ap(gB.w + bb1.w);

            float cn0 = f0 * cc.x + i0 * q0;
            float cn1 = f1 * cc.y + i1 * q1;
            float h0 = o0 * tanh_ap(cn0);
            float h1 = o1 * tanh_ap(cn1);

            *(float2*)&g_c[idx] = make_float2(cn0, cn1);
            *(float2*)&hs_t[idx] = make_float2(h0, h1);
            *(__half2*)&g_h[wbuf][idx] = __floats2half2_rn(h0, h1);
        }

        grid_sync();                            // h(t) visible everywhere before step t+1
    }
}

// ---------------- output projection ----------------
__global__ void out_kernel(const float* __restrict__ W_lin,
                           const float* __restrict__ b_lin,
                           float* __restrict__ out) {
    const int warp = (blockIdx.x * blockDim.x + threadIdx.x) >> 5;
    const int lane = threadIdx.x & 31;
    if (warp >= NT * NG) return;
    const float* hrow = g_hs + (size_t)warp * HH;
    float s = 0.0f;
#pragma unroll 8
    for (int j = lane; j < HH; j += 32)
        s += hrow[j] * W_lin[j];
#pragma unroll
    for (int o = 16; o; o >>= 1)
        s += __shfl_xor_sync(0xFFFFFFFFu, s, o);
    if (lane == 0) out[warp] = s + b_lin[0];
}

// ---------------- host ----------------
extern "C" void kernel_launch(void* const* d_in, const int* in_sizes, int n_in,
                              void* d_out, int out_size) {
    const float* x     = (const float*)d_in[0];
    const float* maskX = (const float*)d_in[1];
    const float* W_ih  = (const float*)d_in[2];
    const float* W_hh  = (const float*)d_in[3];
    const float* b_ih  = (const float*)d_in[4];
    const float* b_hh  = (const float*)d_in[5];
    const float* W_lin = (const float*)d_in[6];
    const float* b_lin = (const float*)d_in[7];
    float* out = (float*)d_out;

    cudaFuncSetAttribute(lstm_persist_kernel,
                         cudaFuncAttributeMaxDynamicSharedMemorySize, DSMEM_BYTES);

    zero_kernel<<<(NGHH + 255) / 256, 256>>>();
    prep_bias_kernel<<<(HH + 255) / 256, 256>>>(b_ih, b_hh);
    prep_W_kernel<<<dim3((KTOT + 255) / 256, G4), 256>>>(W_ih, W_hh);
    prep_xm_kernel<<<dim3((NG * NX) / 256, NT), 256>>>(x, maskX);

    lstm_persist_kernel<<<NBLK, 256, DSMEM_BYTES>>>();

    out_kernel<<<(NT * NG + 7) / 8, 256>>>(W_lin, b_lin, out);
}

// round 9
// speedup vs baseline: 6.0313x; 1.0467x over previous
#include <cuda_runtime.h>
#include <cuda_fp16.h>
#include <stdint.h>
#include <math.h>

#define NT 365
#define NG 512
#define NX 256
#define HH 1024
#define KTOT 1280
#define G4 4096
#define NGHH (NG * HH)
#define NCHUNK 20                    // 4 chunks of xm (K=256) first, then 16 of h (K=1024)
#define STAGE_BYTES 32768            // A(16KB) + B(16KB)
#define NSTAGE 3
#define DSMEM_BYTES (NSTAGE * STAGE_BYTES)
#define NBLK 128

// ---------------- scratch (__device__ globals; no allocation) ----------------
__device__ __half g_h[2][NGHH];                     // ping-pong, fp16
__device__ __half g_Wp[(size_t)G4 * KTOT];          // rows permuted: r' = col*4 + gate
__device__ __half g_xm[(size_t)NT * NG * NX];       // fp16
__device__ float4 g_biasp[HH];                      // per col: (bi, bf, bg, bo)
__device__ unsigned int g_bar_count;
__device__ volatile unsigned int g_bar_gen;

// ---------------- PTX helpers ----------------
static __device__ __forceinline__ uint32_t smem_u32(const void* p) {
    uint32_t a;
    asm("{ .reg .u64 t; cvta.to.shared.u64 t, %1; cvt.u32.u64 %0, t; }" : "=r"(a) : "l"(p));
    return a;
}
#define SWZ(o) ((o) ^ (((o) >> 3) & 0x70))

static __device__ __forceinline__ void cp16(uint32_t dst, const void* src) {
    asm volatile("cp.async.cg.shared.global [%0], [%1], 16;" :: "r"(dst), "l"(src));
}
static __device__ __forceinline__ void cp_commit() {
    asm volatile("cp.async.commit_group;" ::: "memory");
}
template <int N>
static __device__ __forceinline__ void cp_wait() {
    asm volatile("cp.async.wait_group %0;" :: "n"(N) : "memory");
}
static __device__ __forceinline__ void ldm4(uint32_t* r, uint32_t addr) {
    asm volatile("ldmatrix.sync.aligned.m8n8.x4.shared.b16 {%0,%1,%2,%3}, [%4];"
                 : "=r"(r[0]), "=r"(r[1]), "=r"(r[2]), "=r"(r[3]) : "r"(addr));
}
static __device__ __forceinline__ void mma_f16(float* d, const uint32_t* a,
                                               uint32_t b0, uint32_t b1) {
    asm volatile(
        "mma.sync.aligned.m16n8k16.row.col.f32.f16.f16.f32 "
        "{%0,%1,%2,%3}, {%4,%5,%6,%7}, {%8,%9}, {%0,%1,%2,%3};"
        : "+f"(d[0]), "+f"(d[1]), "+f"(d[2]), "+f"(d[3])
        : "r"(a[0]), "r"(a[1]), "r"(a[2]), "r"(a[3]), "r"(b0), "r"(b1));
}
static __device__ __forceinline__ float tanh_ap(float x) {
    float y;
    asm("tanh.approx.f32 %0, %1;" : "=f"(y) : "f"(x));
    return y;
}
static __device__ __forceinline__ float sig_ap(float x) {
    return fmaf(tanh_ap(0.5f * x), 0.5f, 0.5f);
}

// split grid barrier (all NBLK CTAs co-resident: 128 <= 148 SMs)
static __device__ __forceinline__ void bar_arrive(int t) {
    __syncthreads();                         // whole CTA done with step t
    if (threadIdx.x == 0) {
        __threadfence();                     // release: h(t) visible in L2
        if (atomicAdd(&g_bar_count, 1u) == NBLK - 1) {
            g_bar_count = 0;
            __threadfence();
            g_bar_gen = (unsigned)(t + 1);
        }
    }
}
static __device__ __forceinline__ void bar_wait(int t) {
    if (threadIdx.x == 0) {
        while ((int)g_bar_gen < t) { }
        __threadfence();
    }
    __syncthreads();
}

// ---------------- prep kernels ----------------
__global__ void zero_kernel() {
    int i = blockIdx.x * 256 + threadIdx.x;
    if (i < NGHH) g_h[0][i] = __float2half(0.0f);
    if (i == 0) { g_bar_count = 0; g_bar_gen = 0; }
}

__global__ void init_out_kernel(const float* __restrict__ b_lin, float* __restrict__ out) {
    int i = blockIdx.x * 256 + threadIdx.x;
    if (i < NT * NG) out[i] = b_lin[0];
}

__global__ void prep_bias_kernel(const float* __restrict__ b_ih, const float* __restrict__ b_hh) {
    int col = blockIdx.x * 256 + threadIdx.x;
    if (col >= HH) return;
    float4 v;
    v.x = b_ih[col] + b_hh[col];
    v.y = b_ih[HH + col] + b_hh[HH + col];
    v.z = b_ih[2 * HH + col] + b_hh[2 * HH + col];
    v.w = b_ih[3 * HH + col] + b_hh[3 * HH + col];
    g_biasp[col] = v;
}

// W' row r' = col*4 + gate; k cols 0..1023 from W_hh, 1024..1279 from W_ih (fused K)
__global__ void prep_W_kernel(const float* __restrict__ W_ih, const float* __restrict__ W_hh) {
    int k = blockIdx.x * 256 + threadIdx.x;
    int r = blockIdx.y;                       // old row: gate*1024 + col
    if (k >= KTOT) return;
    float v = (k < HH) ? W_hh[(size_t)r * HH + k]
                       : W_ih[(size_t)r * NX + (k - HH)];
    int gate = r >> 10, col = r & 1023;
    g_Wp[(size_t)(col * 4 + gate) * KTOT + k] = __float2half(v);
}

__global__ void prep_xm_kernel(const float* __restrict__ x, const float* __restrict__ maskX) {
    int idx = blockIdx.x * 256 + threadIdx.x;   // 0..NG*NX-1
    int t = blockIdx.y;
    size_t gi = (size_t)t * (NG * NX) + idx;
    g_xm[gi] = __float2half(x[gi] * maskX[idx]);
}

// ---------------- persistent fused LSTM: all 365 steps, c in registers ----------------
// grid 128 = 4 m-groups(128 batch) x 32 col-groups(32 hidden cols x 4 gates = 128 N)
__global__ __launch_bounds__(256, 1) void lstm_persist_kernel(
    const float* __restrict__ W_lin, float* __restrict__ out) {
    extern __shared__ char dsm[];
    const uint32_t sbase = smem_u32(dsm);
    const int tid = threadIdx.x;
    const int w = tid >> 5;
    const int lane = tid & 31;
    const int m0 = (blockIdx.x & 3) * 128;
    const int cgrp = blockIdx.x >> 2;
    const int n0g = cgrp * 128;                 // W' row base (contiguous after permute)

    const int prow = tid >> 3;                  // cp.async: 0..31 (+32*s)
    const int pseg = tid & 7;                   // 16B segment in 128B row

    const int mw = (w & 3) * 32;                // warp m-offset
    const int nw = (w >> 2) * 64;               // warp n-offset
    const int lrow = lane & 15;
    const int lcol16 = (lane >> 4) * 16;        // byte offset of k-half

    const int tg = tid & 15;                    // epilogue col-pair group
    const int rr = tid >> 4;                    // epilogue row group (0..15)

    // per-thread fixed epilogue ownership
    const int ecol = cgrp * 32 + tg * 2;
    const float4 bb0 = g_biasp[ecol];
    const float4 bb1 = g_biasp[ecol + 1];
    const float wl0 = W_lin[ecol];
    const float wl1 = W_lin[ecol + 1];

    float creg[8][2];                           // cell state, register-resident
#pragma unroll
    for (int p = 0; p < 8; ++p) { creg[p][0] = 0.0f; creg[p][1] = 0.0f; }

#pragma unroll 1
    for (int t = 0; t < NT; ++t) {
        const int rbuf = t & 1;
        const int wbuf = (t + 1) & 1;

        float acc[2][8][4];
#pragma unroll
        for (int im = 0; im < 2; ++im)
#pragma unroll
            for (int jn = 0; jn < 8; ++jn)
#pragma unroll
                for (int r = 0; r < 4; ++r) acc[im][jn][r] = 0.0f;

        // chunk order: i=0..3 -> xm (no h dependency), i=4..19 -> h
        auto prefetch = [&](int i, int stage) {
            const uint32_t stb = sbase + stage * STAGE_BYTES;
            const __half* aSrc;
            int astr, ak, bk;
            if (i < 4) {
                aSrc = g_xm + (size_t)t * NG * NX; astr = NX; ak = i * 64; bk = (16 + i) * 64;
            } else {
                aSrc = g_h[rbuf]; astr = HH; ak = (i - 4) * 64; bk = (i - 4) * 64;
            }
#pragma unroll
            for (int s = 0; s < 4; ++s) {
                const int row = prow + s * 32;
                const uint32_t soff = SWZ(row * 128 + pseg * 16);
                cp16(stb + soff,         aSrc + (size_t)(m0 + row) * astr + ak + pseg * 8);
                cp16(stb + 16384 + soff, g_Wp + (size_t)(n0g + row) * KTOT + bk + pseg * 8);
            }
            cp_commit();
        };

        prefetch(0, 0);
        prefetch(1, 1);

        int stage = 0;
        for (int i = 0; i < NCHUNK; ++i) {
            if (i + 1 < NCHUNK) cp_wait<1>();   // chunk i landed (i+1 may be pending)
            else cp_wait<0>();
            __syncthreads();                     // data visible + compute(i-1) done
            if (i + 2 < NCHUNK) {
                if (i + 2 == 4) bar_wait(t);    // h(t-1) must be complete before h prefetch
                int ns = stage + 2; if (ns >= NSTAGE) ns -= NSTAGE;
                prefetch(i + 2, ns);            // writes stage (i-1)%3: safe after barrier
            }

            const uint32_t stb = sbase + stage * STAGE_BYTES;
#pragma unroll
            for (int ks = 0; ks < 4; ++ks) {     // K=16 per mma, 4 per 64-chunk
                const int kb = ks * 32;
                uint32_t ah[2][4], bh[4][4];
#pragma unroll
                for (int im = 0; im < 2; ++im)
                    ldm4(ah[im], stb + SWZ((mw + im * 16 + lrow) * 128 + kb + lcol16));
#pragma unroll
                for (int jb = 0; jb < 4; ++jb)
                    ldm4(bh[jb], stb + 16384 + SWZ((nw + jb * 16 + lrow) * 128 + kb + lcol16));
#pragma unroll
                for (int im = 0; im < 2; ++im)
#pragma unroll
                    for (int jn = 0; jn < 8; ++jn)
                        mma_f16(acc[im][jn], ah[im], bh[jn >> 1][jn & 1], bh[jn >> 1][(jn & 1) + 2]);
            }
            ++stage; if (stage >= NSTAGE) stage = 0;
        }

        // ---- epilogue: fragments -> smem (transpose) -> cell update + fused out dot ----
        float* sT = (float*)dsm;                // 128 x 132 fp32 = 67.6KB < 96KB
        __syncthreads();                        // mainloop smem reads done
#pragma unroll
        for (int im = 0; im < 2; ++im) {
            const int r0 = mw + im * 16 + (lane >> 2);
#pragma unroll
            for (int jn = 0; jn < 8; ++jn) {
                const int nb = nw + jn * 8 + (lane & 3) * 2;
                *(float2*)&sT[r0 * 132 + nb]       = make_float2(acc[im][jn][0], acc[im][jn][1]);
                *(float2*)&sT[(r0 + 8) * 132 + nb] = make_float2(acc[im][jn][2], acc[im][jn][3]);
            }
        }
        __syncthreads();

#pragma unroll
        for (int p = 0; p < 8; ++p) {
            const int row = p * 16 + rr;
            const int b = m0 + row;
            const float4 gA = *(float4*)&sT[row * 132 + tg * 8];
            const float4 gB = *(float4*)&sT[row * 132 + tg * 8 + 4];

            float i0 = sig_ap(gA.x + bb0.x);
            float f0 = sig_ap(gA.y + bb0.y);
            float q0 = tanh_ap(gA.z + bb0.z);
            float o0 = sig_ap(gA.w + bb0.w);
            float i1 = sig_ap(gB.x + bb1.x);
            float f1 = sig_ap(gB.y + bb1.y);
            float q1 = tanh_ap(gB.z + bb1.z);
            float o1 = sig_ap(gB.w + bb1.w);

            float cn0 = f0 * creg[p][0] + i0 * q0;
            float cn1 = f1 * creg[p][1] + i1 * q1;
            creg[p][0] = cn0;
            creg[p][1] = cn1;
            float h0 = o0 * tanh_ap(cn0);
            float h1 = o1 * tanh_ap(cn1);

            *(__half2*)&g_h[wbuf][(size_t)b * HH + ecol] = __floats2half2_rn(h0, h1);

            // fused output projection: reduce over this CTA's 32 cols
            float v = h0 * wl0 + h1 * wl1;
#pragma unroll
            for (int o = 8; o; o >>= 1)
                v += __shfl_xor_sync(0xFFFFFFFFu, v, o);
            if (tg == 0) atomicAdd(&out[t * NG + b], v);
        }

        bar_arrive(t);                          // release h(t); last CTA bumps gen
    }
}

// ---------------- host ----------------
extern "C" void kernel_launch(void* const* d_in, const int* in_sizes, int n_in,
                              void* d_out, int out_size) {
    const float* x     = (const float*)d_in[0];
    const float* maskX = (const float*)d_in[1];
    const float* W_ih  = (const float*)d_in[2];
    const float* W_hh  = (const float*)d_in[3];
    const float* b_ih  = (const float*)d_in[4];
    const float* b_hh  = (const float*)d_in[5];
    const float* W_lin = (const float*)d_in[6];
    const float* b_lin = (const float*)d_in[7];
    float* out = (float*)d_out;

    cudaFuncSetAttribute(lstm_persist_kernel,
                         cudaFuncAttributeMaxDynamicSharedMemorySize, DSMEM_BYTES);

    zero_kernel<<<(NGHH + 255) / 256, 256>>>();
    init_out_kernel<<<(NT * NG + 255) / 256, 256>>>(b_lin, out);
    prep_bias_kernel<<<(HH + 255) / 256, 256>>>(b_ih, b_hh);
    prep_W_kernel<<<dim3((KTOT + 255) / 256, G4), 256>>>(W_ih, W_hh);
    prep_xm_kernel<<<dim3((NG * NX) / 256, NT), 256>>>(x, maskX);

    lstm_persist_kernel<<<NBLK, 256, DSMEM_BYTES>>>(W_lin, out);
}

// round 10
// speedup vs baseline: 6.0401x; 1.0015x over previous
#include <cuda_runtime.h>
#include <cuda_fp16.h>
#include <stdint.h>
#include <math.h>

#define NT 365
#define NG 512
#define NX 256
#define HH 1024
#define KTOT 1280
#define G4 4096
#define NGHH (NG * HH)
#define NCHUNK 20                    // 4 chunks of xm (K=256) first, then 16 of h (K=1024)
#define STAGE_BYTES 32768            // A(16KB) + B(16KB)
#define NSTAGE 3
#define SMEM_ST_OFF (NSTAGE * STAGE_BYTES)
#define DSMEM_BYTES (SMEM_ST_OFF + 128 * 132 * 4)   // stages + dedicated sT = 162KB
#define NBLK 128
#define GRPSZ 32                     // CTAs per m-group barrier

// ---------------- scratch (__device__ globals; no allocation) ----------------
__device__ __half g_h[2][NGHH];                     // ping-pong, fp16
__device__ __half g_Wp[(size_t)G4 * KTOT];          // rows permuted: r' = col*4 + gate
__device__ __half g_xm[(size_t)NT * NG * NX];       // fp16
__device__ float4 g_biasp[HH];                      // per col: (bi, bf, bg, bo)
__device__ unsigned int g_bar_cnt[4 * 32];          // per m-group, padded to 128B
__device__ volatile unsigned int g_bar_gen[4 * 32];

// ---------------- PTX helpers ----------------
static __device__ __forceinline__ uint32_t smem_u32(const void* p) {
    uint32_t a;
    asm("{ .reg .u64 t; cvta.to.shared.u64 t, %1; cvt.u32.u64 %0, t; }" : "=r"(a) : "l"(p));
    return a;
}
#define SWZ(o) ((o) ^ (((o) >> 3) & 0x70))

static __device__ __forceinline__ void cp16(uint32_t dst, const void* src) {
    asm volatile("cp.async.cg.shared.global [%0], [%1], 16;" :: "r"(dst), "l"(src));
}
static __device__ __forceinline__ void cp_commit() {
    asm volatile("cp.async.commit_group;" ::: "memory");
}
template <int N>
static __device__ __forceinline__ void cp_wait() {
    asm volatile("cp.async.wait_group %0;" :: "n"(N) : "memory");
}
static __device__ __forceinline__ void ldm4(uint32_t* r, uint32_t addr) {
    asm volatile("ldmatrix.sync.aligned.m8n8.x4.shared.b16 {%0,%1,%2,%3}, [%4];"
                 : "=r"(r[0]), "=r"(r[1]), "=r"(r[2]), "=r"(r[3]) : "r"(addr));
}
static __device__ __forceinline__ void mma_f16(float* d, const uint32_t* a,
                                               uint32_t b0, uint32_t b1) {
    asm volatile(
        "mma.sync.aligned.m16n8k16.row.col.f32.f16.f16.f32 "
        "{%0,%1,%2,%3}, {%4,%5,%6,%7}, {%8,%9}, {%0,%1,%2,%3};"
        : "+f"(d[0]), "+f"(d[1]), "+f"(d[2]), "+f"(d[3])
        : "r"(a[0]), "r"(a[1]), "r"(a[2]), "r"(a[3]), "r"(b0), "r"(b1));
}
static __device__ __forceinline__ float tanh_ap(float x) {
    float y;
    asm("tanh.approx.f32 %0, %1;" : "=f"(y) : "f"(x));
    return y;
}
static __device__ __forceinline__ float sig_ap(float x) {
    return fmaf(tanh_ap(0.5f * x), 0.5f, 0.5f);
}

// per-m-group split barrier (32 CTAs each; all CTAs co-resident)
static __device__ __forceinline__ void bar_arrive(int mgrp, int t) {
    __syncthreads();                         // whole CTA done with step t
    if (threadIdx.x == 0) {
        __threadfence();                     // release: h(t) visible
        if (atomicAdd(&g_bar_cnt[mgrp * 32], 1u) == GRPSZ - 1) {
            g_bar_cnt[mgrp * 32] = 0;
            __threadfence();
            g_bar_gen[mgrp * 32] = (unsigned)(t + 1);
        }
    }
}
static __device__ __forceinline__ void bar_wait(int mgrp, int t) {
    if (threadIdx.x == 0) {
        while ((int)g_bar_gen[mgrp * 32] < t) { }
        __threadfence();
    }
    __syncthreads();
}

// ---------------- prep kernels ----------------
__global__ void zero_kernel() {
    int i = blockIdx.x * 256 + threadIdx.x;
    if (i < NGHH) g_h[0][i] = __float2half(0.0f);
    if (i < 4 * 32) { g_bar_cnt[i] = 0; g_bar_gen[i] = 0; }
}

__global__ void init_out_kernel(const float* __restrict__ b_lin, float* __restrict__ out) {
    int i = blockIdx.x * 256 + threadIdx.x;
    if (i < NT * NG) out[i] = b_lin[0];
}

__global__ void prep_bias_kernel(const float* __restrict__ b_ih, const float* __restrict__ b_hh) {
    int col = blockIdx.x * 256 + threadIdx.x;
    if (col >= HH) return;
    float4 v;
    v.x = b_ih[col] + b_hh[col];
    v.y = b_ih[HH + col] + b_hh[HH + col];
    v.z = b_ih[2 * HH + col] + b_hh[2 * HH + col];
    v.w = b_ih[3 * HH + col] + b_hh[3 * HH + col];
    g_biasp[col] = v;
}

// W' row r' = col*4 + gate; k cols 0..1023 from W_hh, 1024..1279 from W_ih (fused K)
__global__ void prep_W_kernel(const float* __restrict__ W_ih, const float* __restrict__ W_hh) {
    int k = blockIdx.x * 256 + threadIdx.x;
    int r = blockIdx.y;                       // old row: gate*1024 + col
    if (k >= KTOT) return;
    float v = (k < HH) ? W_hh[(size_t)r * HH + k]
                       : W_ih[(size_t)r * NX + (k - HH)];
    int gate = r >> 10, col = r & 1023;
    g_Wp[(size_t)(col * 4 + gate) * KTOT + k] = __float2half(v);
}

__global__ void prep_xm_kernel(const float* __restrict__ x, const float* __restrict__ maskX) {
    int idx = blockIdx.x * 256 + threadIdx.x;   // 0..NG*NX-1
    int t = blockIdx.y;
    size_t gi = (size_t)t * (NG * NX) + idx;
    g_xm[gi] = __float2half(x[gi] * maskX[idx]);
}

// ---------------- persistent fused LSTM: all 365 steps, c in registers ----------------
// grid 128 = 4 m-groups(128 batch) x 32 col-groups(32 hidden cols x 4 gates = 128 N)
__global__ __launch_bounds__(256, 1) void lstm_persist_kernel(
    const float* __restrict__ W_lin, float* __restrict__ out) {
    extern __shared__ char dsm[];
    const uint32_t sbase = smem_u32(dsm);
    float* sT = (float*)(dsm + SMEM_ST_OFF);    // dedicated epilogue buffer
    const int tid = threadIdx.x;
    const int w = tid >> 5;
    const int lane = tid & 31;
    const int mgrp = blockIdx.x & 3;
    const int m0 = mgrp * 128;
    const int cgrp = blockIdx.x >> 2;
    const int n0g = cgrp * 128;                 // W' row base (contiguous after permute)

    const int prow = tid >> 3;                  // cp.async: 0..31 (+32*s)
    const int pseg = tid & 7;                   // 16B segment in 128B row

    const int mw = (w & 3) * 32;                // warp m-offset
    const int nw = (w >> 2) * 64;               // warp n-offset
    const int lrow = lane & 15;
    const int lcol16 = (lane >> 4) * 16;        // byte offset of k-half

    const int tg = tid & 15;                    // epilogue col-pair group
    const int rr = tid >> 4;                    // epilogue row group (0..15)

    // per-thread fixed epilogue ownership
    const int ecol = cgrp * 32 + tg * 2;
    const float4 bb0 = g_biasp[ecol];
    const float4 bb1 = g_biasp[ecol + 1];
    const float wl0 = W_lin[ecol];
    const float wl1 = W_lin[ecol + 1];

    float creg[8][2];                           // cell state, register-resident
#pragma unroll
    for (int p = 0; p < 8; ++p) { creg[p][0] = 0.0f; creg[p][1] = 0.0f; }

    // chunk order: i=0..3 -> xm (no h dependency), i=4..19 -> h(t-1)
    auto prefetch = [&](int tt, int i, int stage) {
        const uint32_t stb = sbase + stage * STAGE_BYTES;
        const __half* aSrc;
        int astr, ak, bk;
        if (i < 4) {
            aSrc = g_xm + (size_t)tt * NG * NX; astr = NX; ak = i * 64; bk = (16 + i) * 64;
        } else {
            aSrc = g_h[tt & 1]; astr = HH; ak = (i - 4) * 64; bk = (i - 4) * 64;
        }
#pragma unroll
        for (int s = 0; s < 4; ++s) {
            const int row = prow + s * 32;
            const uint32_t soff = SWZ(row * 128 + pseg * 16);
            cp16(stb + soff,         aSrc + (size_t)(m0 + row) * astr + ak + pseg * 8);
            cp16(stb + 16384 + soff, g_Wp + (size_t)(n0g + row) * KTOT + bk + pseg * 8);
        }
        cp_commit();
    };

    // prologue for t=0 (x chunks only; later steps issue these in the prior epilogue)
    prefetch(0, 0, 0);
    prefetch(0, 1, 1);

#pragma unroll 1
    for (int t = 0; t < NT; ++t) {
        const int wbuf = (t + 1) & 1;

        float acc[2][8][4];
#pragma unroll
        for (int im = 0; im < 2; ++im)
#pragma unroll
            for (int jn = 0; jn < 8; ++jn)
#pragma unroll
                for (int r = 0; r < 4; ++r) acc[im][jn][r] = 0.0f;

        int stage = 0;
        for (int i = 0; i < NCHUNK; ++i) {
            if (i + 1 < NCHUNK) cp_wait<1>();   // chunk i landed (i+1 may be pending)
            else cp_wait<0>();
            __syncthreads();                     // data visible + compute(i-1) done
            if (i + 2 < NCHUNK) {
                if (i + 2 == 4) bar_wait(mgrp, t);  // h(t-1) of this m-group complete
                int ns = stage + 2; if (ns >= NSTAGE) ns -= NSTAGE;
                prefetch(t, i + 2, ns);         // writes stage (i-1)%3: safe after barrier
            }

            const uint32_t stb = sbase + stage * STAGE_BYTES;
#pragma unroll
            for (int ks = 0; ks < 4; ++ks) {     // K=16 per mma, 4 per 64-chunk
                const int kb = ks * 32;
                uint32_t ah[2][4], bh[4][4];
#pragma unroll
                for (int im = 0; im < 2; ++im)
                    ldm4(ah[im], stb + SWZ((mw + im * 16 + lrow) * 128 + kb + lcol16));
#pragma unroll
                for (int jb = 0; jb < 4; ++jb)
                    ldm4(bh[jb], stb + 16384 + SWZ((nw + jb * 16 + lrow) * 128 + kb + lcol16));
#pragma unroll
                for (int im = 0; im < 2; ++im)
#pragma unroll
                    for (int jn = 0; jn < 8; ++jn)
                        mma_f16(acc[im][jn], ah[im], bh[jn >> 1][jn & 1], bh[jn >> 1][(jn & 1) + 2]);
            }
            ++stage; if (stage >= NSTAGE) stage = 0;
        }

        __syncthreads();                        // all warps done reading stages

        // issue next step's x-chunk prefetches NOW; they land during the epilogue
        if (t + 1 < NT) {
            prefetch(t + 1, 0, 0);
            prefetch(t + 1, 1, 1);
        }

        // ---- epilogue: fragments -> sT (transpose) -> cell update + fused out dot ----
#pragma unroll
        for (int im = 0; im < 2; ++im) {
            const int r0 = mw + im * 16 + (lane >> 2);
#pragma unroll
            for (int jn = 0; jn < 8; ++jn) {
                const int nb = nw + jn * 8 + (lane & 3) * 2;
                *(float2*)&sT[r0 * 132 + nb]       = make_float2(acc[im][jn][0], acc[im][jn][1]);
                *(float2*)&sT[(r0 + 8) * 132 + nb] = make_float2(acc[im][jn][2], acc[im][jn][3]);
            }
        }
        __syncthreads();

#pragma unroll
        for (int p = 0; p < 8; ++p) {
            const int row = p * 16 + rr;
            const int b = m0 + row;
            const float4 gA = *(float4*)&sT[row * 132 + tg * 8];
            const float4 gB = *(float4*)&sT[row * 132 + tg * 8 + 4];

            float i0 = sig_ap(gA.x + bb0.x);
            float f0 = sig_ap(gA.y + bb0.y);
            float q0 = tanh_ap(gA.z + bb0.z);
            float o0 = sig_ap(gA.w + bb0.w);
            float i1 = sig_ap(gB.x + bb1.x);
            float f1 = sig_ap(gB.y + bb1.y);
            float q1 = tanh_ap(gB.z + bb1.z);
            float o1 = sig_ap(gB.w + bb1.w);

            float cn0 = f0 * creg[p][0] + i0 * q0;
            float cn1 = f1 * creg[p][1] + i1 * q1;
            creg[p][0] = cn0;
            creg[p][1] = cn1;
            float h0 = o0 * tanh_ap(cn0);
            float h1 = o1 * tanh_ap(cn1);

            *(__half2*)&g_h[wbuf][(size_t)b * HH + ecol] = __floats2half2_rn(h0, h1);

            // fused output projection: reduce over this CTA's 32 cols
            float v = h0 * wl0 + h1 * wl1;
#pragma unroll
            for (int o = 8; o; o >>= 1)
                v += __shfl_xor_sync(0xFFFFFFFFu, v, o);
            if (tg == 0) atomicAdd(&out[t * NG + b], v);
        }

        bar_arrive(mgrp, t);                    // release h(t) for this m-group
    }
}

// ---------------- host ----------------
extern "C" void kernel_launch(void* const* d_in, const int* in_sizes, int n_in,
                              void* d_out, int out_size) {
    const float* x     = (const float*)d_in[0];
    const float* maskX = (const float*)d_in[1];
    const float* W_ih  = (const float*)d_in[2];
    const float* W_hh  = (const float*)d_in[3];
    const float* b_ih  = (const float*)d_in[4];
    const float* b_hh  = (const float*)d_in[5];
    const float* W_lin = (const float*)d_in[6];
    const float* b_lin = (const float*)d_in[7];
    float* out = (float*)d_out;

    cudaFuncSetAttribute(lstm_persist_kernel,
                         cudaFuncAttributeMaxDynamicSharedMemorySize, DSMEM_BYTES);

    zero_kernel<<<(NGHH + 255) / 256, 256>>>();
    init_out_kernel<<<(NT * NG + 255) / 256, 256>>>(b_lin, out);
    prep_bias_kernel<<<(HH + 255) / 256, 256>>>(b_ih, b_hh);
    prep_W_kernel<<<dim3((KTOT + 255) / 256, G4), 256>>>(W_ih, W_hh);
    prep_xm_kernel<<<dim3((NG * NX) / 256, NT), 256>>>(x, maskX);

    lstm_persist_kernel<<<NBLK, 256, DSMEM_BYTES>>>(W_lin, out);
}